// round 16
// baseline (speedup 1.0000x reference)
#include <cuda_runtime.h>
#include <cuda_fp16.h>
#include <cstdint>

// ===========================================================================
// GCN 3-layer encoder.
//  - GEMMs: single-pass fp16 mma.sync m16n8k16, fp32 acc. FULL-K smem
//    residency (one cp.async stage + one barrier per CTA). Warp tile
//    32rows x N/2cols, paired-n-frag ldsm_x4 for B, 3 CTA/SM.
//    Epilogue: G = fp16(dinv * (A@W)).
//  - Factored norm: out_i = b + dinv_i*(G_i + sum G_src).
//  - CSR-pull aggregation on fp16 G, fp32 accumulate, bias+ReLU fused.
//  - prep_all zeroes cnt (no memset launch). gemm1 = launch #5 (ncu window).
// ===========================================================================

#define MAX_NODES 100000
#define MAX_EDGES 1000000

__device__ __half         g_G  [(size_t)MAX_NODES * 128];   // fp16 messages
__device__ __half         g_F  [(size_t)MAX_NODES * 128];   // fp16 node feats / x16
__device__ int            g_cnt   [MAX_NODES];
__device__ int            g_rowptr[MAX_NODES + 1];
__device__ int            g_cursor[MAX_NODES];
__device__ float          g_dinv  [MAX_NODES];
__device__ int            g_esrc  [MAX_EDGES];
__device__ int            g_bsum  [1024];
__device__ int            g_boff  [1024];
__device__ unsigned short g_B1[128 * 128];
__device__ unsigned short g_B2[128 * 64];
__device__ unsigned short g_B3[64 * 64];

// ---------------------------------------------------------------------------
// helpers
// ---------------------------------------------------------------------------
__device__ __forceinline__ uint32_t smem_u32(const void* p) {
    uint32_t a;
    asm("{ .reg .u64 t; cvta.to.shared.u64 t, %1; cvt.u32.u64 %0, t; }"
        : "=r"(a) : "l"(p));
    return a;
}

__device__ __forceinline__ uint32_t h2_as_u32(__half2 h) {
    return *reinterpret_cast<uint32_t*>(&h);
}

__device__ __forceinline__ void cp_async16(uint32_t smem_addr, const void* gptr) {
    asm volatile("cp.async.cg.shared.global [%0], [%1], 16;"
                 :: "r"(smem_addr), "l"(gptr) : "memory");
}

__device__ __forceinline__ void cp_async_wait_all() {
    asm volatile("cp.async.commit_group;" ::: "memory");
    asm volatile("cp.async.wait_group 0;" ::: "memory");
}

__device__ __forceinline__ void ldsm_x4(uint32_t& r0, uint32_t& r1,
                                        uint32_t& r2, uint32_t& r3, uint32_t addr) {
    asm volatile("ldmatrix.sync.aligned.m8n8.x4.shared.b16 {%0,%1,%2,%3}, [%4];"
                 : "=r"(r0), "=r"(r1), "=r"(r2), "=r"(r3) : "r"(addr));
}

__device__ __forceinline__ void mma_fp16(float* c, uint32_t a0, uint32_t a1,
                                         uint32_t a2, uint32_t a3,
                                         uint32_t b0, uint32_t b1) {
    asm volatile(
        "mma.sync.aligned.m16n8k16.row.col.f32.f16.f16.f32 "
        "{%0,%1,%2,%3}, {%4,%5,%6,%7}, {%8,%9}, {%0,%1,%2,%3};"
        : "+f"(c[0]), "+f"(c[1]), "+f"(c[2]), "+f"(c[3])
        : "r"(a0), "r"(a1), "r"(a2), "r"(a3), "r"(b0), "r"(b1));
}

// ---------------------------------------------------------------------------
// CSR build
// ---------------------------------------------------------------------------
__global__ void hist_kernel(const int* __restrict__ dst, int* __restrict__ cnt, int m) {
    int e = blockIdx.x * blockDim.x + threadIdx.x;
    if (e < m) atomicAdd(&cnt[dst[e]], 1);
}

__global__ void dinv_kernel(const int* __restrict__ cnt, float* __restrict__ dinv, int n) {
    int i = blockIdx.x * blockDim.x + threadIdx.x;
    if (i < n) dinv[i] = rsqrtf((float)(cnt[i] + 1));
}

__global__ __launch_bounds__(256)
void scan_p1_kernel(const int* __restrict__ cnt, int* __restrict__ bsum, int n) {
    __shared__ int red[256];
    int base = blockIdx.x * 1024;
    int t = threadIdx.x;
    int s = 0;
#pragma unroll
    for (int j = 0; j < 4; j++) {
        int i = base + t * 4 + j;
        if (i < n) s += cnt[i];
    }
    red[t] = s;
    __syncthreads();
    for (int d = 128; d > 0; d >>= 1) {
        if (t < d) red[t] += red[t + d];
        __syncthreads();
    }
    if (t == 0) bsum[blockIdx.x] = red[0];
}

__global__ __launch_bounds__(256)
void scan_p2_kernel(const int* __restrict__ bsum, int* __restrict__ boff,
                    int* __restrict__ rowptr, int n, int nb) {
    __shared__ int sm[256];
    int t = threadIdx.x;
    int v = (t < nb) ? bsum[t] : 0;
    sm[t] = v;
    __syncthreads();
    for (int d = 1; d < 256; d <<= 1) {
        int u = (t >= d) ? sm[t - d] : 0;
        __syncthreads();
        sm[t] += u;
        __syncthreads();
    }
    if (t < nb) boff[t] = sm[t] - v;
    if (t == 255) rowptr[n] = sm[255];
}

__global__ __launch_bounds__(256)
void scan_p3_kernel(const int* __restrict__ cnt, const int* __restrict__ boff,
                    int* __restrict__ rowptr, int* __restrict__ cursor, int n) {
    __shared__ int sm[256];
    int base = blockIdx.x * 1024;
    int t = threadIdx.x;
    int c[4];
    int s = 0;
#pragma unroll
    for (int j = 0; j < 4; j++) {
        int i = base + t * 4 + j;
        c[j] = (i < n) ? cnt[i] : 0;
        s += c[j];
    }
    sm[t] = s;
    __syncthreads();
    for (int d = 1; d < 256; d <<= 1) {
        int u = (t >= d) ? sm[t - d] : 0;
        __syncthreads();
        sm[t] += u;
        __syncthreads();
    }
    int run = boff[blockIdx.x] + sm[t] - s;
#pragma unroll
    for (int j = 0; j < 4; j++) {
        int i = base + t * 4 + j;
        if (i < n) { rowptr[i] = run; cursor[i] = run; }
        run += c[j];
    }
}

__global__ void fill_kernel(const int* __restrict__ src, const int* __restrict__ dst,
                            int* __restrict__ cursor, int* __restrict__ esrc, int m) {
    int e = blockIdx.x * blockDim.x + threadIdx.x;
    if (e >= m) return;
    int s = src[e];
    int d = dst[e];
    int pos = atomicAdd(&cursor[d], 1);
    esrc[pos] = s;
}

// ---------------------------------------------------------------------------
// Fused prep: zero cnt; W1/2/3 -> fp16 transposed [n][k]; x -> fp16 into F.
// ---------------------------------------------------------------------------
__device__ __forceinline__ void wcvt(const float* W, unsigned short* Bt,
                                     int idx, int K, int N) {
    int n = idx % N;
    int k = idx / N;
    Bt[n * K + k] = __half_as_ushort(__float2half_rn(W[idx]));
}

__global__ void prep_all_kernel(const float* __restrict__ W1,
                                const float* __restrict__ W2,
                                const float* __restrict__ W3,
                                const float* __restrict__ x, __half* __restrict__ F,
                                unsigned short* __restrict__ B1,
                                unsigned short* __restrict__ B2,
                                unsigned short* __restrict__ B3,
                                int* __restrict__ cnt, int n) {
    int idx = blockIdx.x * 256 + threadIdx.x;
    if (idx < n) cnt[idx] = 0;
    if (idx < 16384) {
        wcvt(W1, B1, idx, 128, 128);
    } else if (idx < 16384 + 8192) {
        wcvt(W2, B2, idx - 16384, 128, 64);
    } else if (idx < 16384 + 8192 + 4096) {
        wcvt(W3, B3, idx - 16384 - 8192, 64, 64);
    } else {
        int j = idx - 28672;
        if (j < n * 32) {
            float4 v = ((const float4*)x)[j];
            uint2 p;
            p.x = h2_as_u32(__floats2half2_rn(v.x, v.y));
            p.y = h2_as_u32(__floats2half2_rn(v.z, v.w));
            ((uint2*)F)[j] = p;
        }
    }
}

// ---------------------------------------------------------------------------
// Tensor-core GEMM: G[M,N] = fp16( dinv[r] * (A[M,K] @ W[K,N]) ), all fp16.
// FULL K in smem: one cp.async stage + one barrier, then all K/16 kk steps.
// Warp tile 32 rows x N/2 cols (4x2 warp grid); paired-n-frag ldsm_x4 for B.
// ---------------------------------------------------------------------------
template <int K, int N>
__global__ __launch_bounds__(256, 3)
void gemm_mma_kernel(const __half* __restrict__ A,
                     const unsigned short* __restrict__ B,
                     const float* __restrict__ dinv,
                     __half* __restrict__ C, int M) {
    constexpr int SA = (K + 8) * 2;      // padded row stride, bytes
    constexpr int ABY = 128 * SA;
    constexpr int C16 = K / 8;           // 16B chunks per row
    extern __shared__ char smem[];
    char* sA = smem;
    char* sB = smem + ABY;

    const int tid = threadIdx.x;
    const int wid = tid >> 5;
    const int lane = tid & 31;
    const int wm = wid & 3;              // 4 M-warps (32 rows)
    const int wn = wid >> 2;             // 2 N-warps (N/2 cols)
    const int rowBase = blockIdx.x * 128;

    constexpr int NF = N / 16;           // n-frags per warp
    float acc[2][NF][4];
#pragma unroll
    for (int mf = 0; mf < 2; mf++)
#pragma unroll
        for (int nf = 0; nf < NF; nf++) {
            acc[mf][nf][0] = 0.f; acc[mf][nf][1] = 0.f;
            acc[mf][nf][2] = 0.f; acc[mf][nf][3] = 0.f;
        }

    const uint32_t aS = smem_u32(sA);
    const uint32_t bS = smem_u32(sB);
    const uint32_t aoff = (uint32_t)(wm * 32 + (lane & 15)) * SA + (uint32_t)(lane >> 4) * 16;
    // paired-n-frag B address: lanes 0-7 nf rows klo, 8-15 nf rows khi,
    // 16-23 nf+1 rows klo, 24-31 nf+1 rows khi
    const uint32_t bbase = bS
                         + (uint32_t)(wn * (N / 2) + (lane & 7) + ((lane >> 4) ? 8 : 0)) * SA
                         + (uint32_t)((lane >> 3) & 1) * 16;

    // --- single stage: full B tile + full A tile ---
    for (int i = tid; i < N * C16; i += 256) {
        int r = i / C16, c = i % C16;
        cp_async16(bS + (uint32_t)(r * SA + c * 16), &B[(size_t)r * K + c * 8]);
    }
    for (int i = tid; i < 128 * C16; i += 256) {
        int r = i / C16, c = i % C16;
        int row = rowBase + r;
        if (row < M)
            cp_async16(aS + (uint32_t)(r * SA + c * 16), &A[(size_t)row * K + c * 8]);
    }
    cp_async_wait_all();
    __syncthreads();

    // --- compute: all K/16 steps ---
#pragma unroll
    for (int kk = 0; kk < K / 16; kk++) {
        uint32_t a0[4], a1[4];
        ldsm_x4(a0[0], a0[1], a0[2], a0[3], aS + aoff + kk * 32);
        ldsm_x4(a1[0], a1[1], a1[2], a1[3], aS + aoff + 16 * SA + kk * 32);
#pragma unroll
        for (int np = 0; np < NF / 2; np++) {
            uint32_t b0, b1, b2, b3;
            ldsm_x4(b0, b1, b2, b3, bbase + (uint32_t)(np * 16) * SA + kk * 32);
            mma_fp16(acc[0][2 * np],     a0[0], a0[1], a0[2], a0[3], b0, b1);
            mma_fp16(acc[1][2 * np],     a1[0], a1[1], a1[2], a1[3], b0, b1);
            mma_fp16(acc[0][2 * np + 1], a0[0], a0[1], a0[2], a0[3], b2, b3);
            mma_fp16(acc[1][2 * np + 1], a1[0], a1[1], a1[2], a1[3], b2, b3);
        }
    }

    // epilogue: scale by dinv[row], convert to fp16, store
    int colBase = wn * (N / 2) + (lane & 3) * 2;
#pragma unroll
    for (int mf = 0; mf < 2; mf++) {
        int r0 = rowBase + wm * 32 + mf * 16 + (lane >> 2);
        float s0 = (r0 < M)     ? dinv[r0]     : 0.f;
        float s1 = (r0 + 8 < M) ? dinv[r0 + 8] : 0.f;
#pragma unroll
        for (int nf = 0; nf < NF; nf++) {
            int c0 = colBase + nf * 8;
            if (r0 < M)
                *(__half2*)&C[(size_t)r0 * N + c0] =
                    __floats2half2_rn(acc[mf][nf][0] * s0, acc[mf][nf][1] * s0);
            if (r0 + 8 < M)
                *(__half2*)&C[(size_t)(r0 + 8) * N + c0] =
                    __floats2half2_rn(acc[mf][nf][2] * s1, acc[mf][nf][3] * s1);
        }
    }
}

// ---------------------------------------------------------------------------
// CSR pull aggregation on fp16 G: out_i = b + dinv_i*(G_i + sum G_src).
// OUTHALF=1 -> fp16 feature output; else fp32 (final layer -> d_out).
// ---------------------------------------------------------------------------
template <int F, int RELU, int OUTHALF>
__global__ __launch_bounds__(256)
void aggregate_kernel(const __half* __restrict__ G,
                      const int* __restrict__ rowptr,
                      const int* __restrict__ esrc,
                      const float* __restrict__ dinv,
                      const float* __restrict__ bias,
                      void* __restrict__ Outp, int n) {
    constexpr int L = F / 4;
    constexpr int NB = 256 / L;
    int i = blockIdx.x * NB + (threadIdx.x / L);
    int c = threadIdx.x % L;
    if (i >= n) return;

    const uint2* Gc = (const uint2*)G + c;
    constexpr int RS = F / 4;

    float2 a0, a1;
    {
        uint2 u = __ldg(&Gc[(size_t)i * RS]);
        a0 = __half22float2(*reinterpret_cast<__half2*>(&u.x));
        a1 = __half22float2(*reinterpret_cast<__half2*>(&u.y));
    }

    int k   = rowptr[i];
    int end = rowptr[i + 1];

    for (; k + 3 < end; k += 4) {
        int s0 = __ldg(&esrc[k]);
        int s1 = __ldg(&esrc[k + 1]);
        int s2 = __ldg(&esrc[k + 2]);
        int s3 = __ldg(&esrc[k + 3]);
        uint2 u0 = __ldg(&Gc[(size_t)s0 * RS]);
        uint2 u1 = __ldg(&Gc[(size_t)s1 * RS]);
        uint2 u2 = __ldg(&Gc[(size_t)s2 * RS]);
        uint2 u3 = __ldg(&Gc[(size_t)s3 * RS]);
        float2 f;
        f = __half22float2(*reinterpret_cast<__half2*>(&u0.x)); a0.x += f.x; a0.y += f.y;
        f = __half22float2(*reinterpret_cast<__half2*>(&u0.y)); a1.x += f.x; a1.y += f.y;
        f = __half22float2(*reinterpret_cast<__half2*>(&u1.x)); a0.x += f.x; a0.y += f.y;
        f = __half22float2(*reinterpret_cast<__half2*>(&u1.y)); a1.x += f.x; a1.y += f.y;
        f = __half22float2(*reinterpret_cast<__half2*>(&u2.x)); a0.x += f.x; a0.y += f.y;
        f = __half22float2(*reinterpret_cast<__half2*>(&u2.y)); a1.x += f.x; a1.y += f.y;
        f = __half22float2(*reinterpret_cast<__half2*>(&u3.x)); a0.x += f.x; a0.y += f.y;
        f = __half22float2(*reinterpret_cast<__half2*>(&u3.y)); a1.x += f.x; a1.y += f.y;
    }
    for (; k < end; k++) {
        int s0 = __ldg(&esrc[k]);
        uint2 u0 = __ldg(&Gc[(size_t)s0 * RS]);
        float2 f;
        f = __half22float2(*reinterpret_cast<__half2*>(&u0.x)); a0.x += f.x; a0.y += f.y;
        f = __half22float2(*reinterpret_cast<__half2*>(&u0.y)); a1.x += f.x; a1.y += f.y;
    }

    float di = dinv[i];
    float4 b = ((const float4*)bias)[c];
    float4 o;
    o.x = fmaf(a0.x, di, b.x);
    o.y = fmaf(a0.y, di, b.y);
    o.z = fmaf(a1.x, di, b.z);
    o.w = fmaf(a1.y, di, b.w);
    if (RELU) {
        o.x = fmaxf(o.x, 0.f); o.y = fmaxf(o.y, 0.f);
        o.z = fmaxf(o.z, 0.f); o.w = fmaxf(o.w, 0.f);
    }
    if (OUTHALF) {
        __half* Out = (__half*)Outp;
        uint2 p;
        p.x = h2_as_u32(__floats2half2_rn(o.x, o.y));
        p.y = h2_as_u32(__floats2half2_rn(o.z, o.w));
        *(uint2*)&Out[(size_t)i * F + c * 4] = p;
    } else {
        ((float4*)Outp)[(size_t)i * L + c] = o;
    }
}

// ---------------------------------------------------------------------------
// Launch: prep(1,zero cnt), hist(2), dinv(3), scan_p1(4), gemm1(5 = ncu),
//         scan_p2, scan_p3, fill, then agg/gemm chain.
// ---------------------------------------------------------------------------
extern "C" void kernel_launch(void* const* d_in, const int* in_sizes, int n_in,
                              void* d_out, int out_size) {
    const float* x  = (const float*)d_in[0];
    const int*   ei = (const int*)  d_in[1];
    const float* W1 = (const float*)d_in[2];
    const float* b1 = (const float*)d_in[3];
    const float* W2 = (const float*)d_in[4];
    const float* b2 = (const float*)d_in[5];
    const float* W3 = (const float*)d_in[6];
    const float* b3 = (const float*)d_in[7];

    const int n = in_sizes[0] / 128;
    const int m = in_sizes[1] / 2;
    const int* src = ei;
    const int* dst = ei + m;

    float* dinv;
    __half *G, *F;
    int *cnt, *rowptr, *cursor, *bsum, *boff, *esrc;
    unsigned short *B1, *B2, *B3;
    cudaGetSymbolAddress((void**)&G,      g_G);
    cudaGetSymbolAddress((void**)&F,      g_F);
    cudaGetSymbolAddress((void**)&cnt,    g_cnt);
    cudaGetSymbolAddress((void**)&rowptr, g_rowptr);
    cudaGetSymbolAddress((void**)&cursor, g_cursor);
    cudaGetSymbolAddress((void**)&dinv,   g_dinv);
    cudaGetSymbolAddress((void**)&esrc,   g_esrc);
    cudaGetSymbolAddress((void**)&bsum,   g_bsum);
    cudaGetSymbolAddress((void**)&boff,   g_boff);
    cudaGetSymbolAddress((void**)&B1,     g_B1);
    cudaGetSymbolAddress((void**)&B2,     g_B2);
    cudaGetSymbolAddress((void**)&B3,     g_B3);

    const int T = 256;
    const int nb = (n + 1023) / 1024;

    constexpr int SM1 = 128 * 272 + 128 * 272;  // 69632 (K=128, N=128)
    constexpr int SM2 = 128 * 272 + 64 * 272;   // 52224 (K=128, N=64)
    constexpr int SM3 = 128 * 144 + 64 * 144;   // 27648 (K=64,  N=64)
    cudaFuncSetAttribute(gemm_mma_kernel<128, 128>, cudaFuncAttributeMaxDynamicSharedMemorySize, SM1);
    cudaFuncSetAttribute(gemm_mma_kernel<128, 64>,  cudaFuncAttributeMaxDynamicSharedMemorySize, SM2);
    cudaFuncSetAttribute(gemm_mma_kernel<64, 64>,   cudaFuncAttributeMaxDynamicSharedMemorySize, SM3);

    const int GB = (n + 127) / 128;

    // 1-4: fused prep (zero cnt + W cvt + x->fp16), degree, dinv, scan_p1
    prep_all_kernel<<<(28672 + n * 32 + 255) / 256, 256>>>(
        W1, W2, W3, x, F, B1, B2, B3, cnt, n);
    hist_kernel<<<(m + T - 1) / T, T>>>(dst, cnt, m);
    dinv_kernel<<<(n + T - 1) / T, T>>>(cnt, dinv, n);
    scan_p1_kernel<<<nb, 256>>>(cnt, bsum, n);
    // 5: GEMM1 (ncu window)
    gemm_mma_kernel<128, 128><<<GB, 256, SM1>>>(F, B1, dinv, G, n);
    // 6-8: rest of CSR
    scan_p2_kernel<<<1, 256>>>(bsum, boff, rowptr, n, nb);
    scan_p3_kernel<<<nb, 256>>>(cnt, boff, rowptr, cursor, n);
    fill_kernel<<<(m + T - 1) / T, T>>>(src, dst, cursor, esrc, m);
    // 9-13: aggregate / gemm chain
    aggregate_kernel<128, 1, 1><<<(n + 7) / 8, 256>>>(G, rowptr, esrc, dinv, b1, F, n);
    gemm_mma_kernel<128, 64><<<GB, 256, SM2>>>(F, B2, dinv, G, n);
    aggregate_kernel<64, 1, 1><<<(n + 15) / 16, 256>>>(G, rowptr, esrc, dinv, b2, F, n);
    gemm_mma_kernel<64, 64><<<GB, 256, SM3>>>(F, B3, dinv, G, n);
    aggregate_kernel<64, 0, 0><<<(n + 15) / 16, 256>>>(G, rowptr, esrc, dinv, b3,
                                                       d_out, n);
}

// round 17
// speedup vs baseline: 1.1309x; 1.1309x over previous
#include <cuda_runtime.h>
#include <cuda_fp16.h>
#include <cstdint>

// ===========================================================================
// GCN 3-layer encoder.  (Revert of R16 full-K experiment -> R15 config.)
//  - GEMMs: single-pass fp16 mma.sync m16n8k16, fp32 acc. KC=64 two-chunk
//    cp.async staging (36.9KB smem, 3 CTA/SM). Warp tile 32rows x N/2cols,
//    paired-n-frag ldsm_x4 for B. Epilogue: G = fp16(dinv * (A@W)).
//  - Factored norm: out_i = b + dinv_i*(G_i + sum G_src).
//  - CSR-pull aggregation on fp16 G, fp32 accumulate, bias+ReLU fused.
//  - cnt zeroing fused into prep_all (one fewer launch vs R15).
// ===========================================================================

#define MAX_NODES 100000
#define MAX_EDGES 1000000

__device__ __half         g_G  [(size_t)MAX_NODES * 128];   // fp16 messages
__device__ __half         g_F  [(size_t)MAX_NODES * 128];   // fp16 node feats / x16
__device__ int            g_cnt   [MAX_NODES];
__device__ int            g_rowptr[MAX_NODES + 1];
__device__ int            g_cursor[MAX_NODES];
__device__ float          g_dinv  [MAX_NODES];
__device__ int            g_esrc  [MAX_EDGES];
__device__ int            g_bsum  [1024];
__device__ int            g_boff  [1024];
__device__ unsigned short g_B1[128 * 128];
__device__ unsigned short g_B2[128 * 64];
__device__ unsigned short g_B3[64 * 64];

// ---------------------------------------------------------------------------
// helpers
// ---------------------------------------------------------------------------
__device__ __forceinline__ uint32_t smem_u32(const void* p) {
    uint32_t a;
    asm("{ .reg .u64 t; cvta.to.shared.u64 t, %1; cvt.u32.u64 %0, t; }"
        : "=r"(a) : "l"(p));
    return a;
}

__device__ __forceinline__ uint32_t h2_as_u32(__half2 h) {
    return *reinterpret_cast<uint32_t*>(&h);
}

__device__ __forceinline__ void cp_async16(uint32_t smem_addr, const void* gptr) {
    asm volatile("cp.async.cg.shared.global [%0], [%1], 16;"
                 :: "r"(smem_addr), "l"(gptr) : "memory");
}

__device__ __forceinline__ void cp_async_wait_all() {
    asm volatile("cp.async.commit_group;" ::: "memory");
    asm volatile("cp.async.wait_group 0;" ::: "memory");
}

__device__ __forceinline__ void ldsm_x4(uint32_t& r0, uint32_t& r1,
                                        uint32_t& r2, uint32_t& r3, uint32_t addr) {
    asm volatile("ldmatrix.sync.aligned.m8n8.x4.shared.b16 {%0,%1,%2,%3}, [%4];"
                 : "=r"(r0), "=r"(r1), "=r"(r2), "=r"(r3) : "r"(addr));
}

__device__ __forceinline__ void mma_fp16(float* c, uint32_t a0, uint32_t a1,
                                         uint32_t a2, uint32_t a3,
                                         uint32_t b0, uint32_t b1) {
    asm volatile(
        "mma.sync.aligned.m16n8k16.row.col.f32.f16.f16.f32 "
        "{%0,%1,%2,%3}, {%4,%5,%6,%7}, {%8,%9}, {%0,%1,%2,%3};"
        : "+f"(c[0]), "+f"(c[1]), "+f"(c[2]), "+f"(c[3])
        : "r"(a0), "r"(a1), "r"(a2), "r"(a3), "r"(b0), "r"(b1));
}

// ---------------------------------------------------------------------------
// CSR build
// ---------------------------------------------------------------------------
__global__ void hist_kernel(const int* __restrict__ dst, int* __restrict__ cnt, int m) {
    int e = blockIdx.x * blockDim.x + threadIdx.x;
    if (e < m) atomicAdd(&cnt[dst[e]], 1);
}

__global__ void dinv_kernel(const int* __restrict__ cnt, float* __restrict__ dinv, int n) {
    int i = blockIdx.x * blockDim.x + threadIdx.x;
    if (i < n) dinv[i] = rsqrtf((float)(cnt[i] + 1));
}

__global__ __launch_bounds__(256)
void scan_p1_kernel(const int* __restrict__ cnt, int* __restrict__ bsum, int n) {
    __shared__ int red[256];
    int base = blockIdx.x * 1024;
    int t = threadIdx.x;
    int s = 0;
#pragma unroll
    for (int j = 0; j < 4; j++) {
        int i = base + t * 4 + j;
        if (i < n) s += cnt[i];
    }
    red[t] = s;
    __syncthreads();
    for (int d = 128; d > 0; d >>= 1) {
        if (t < d) red[t] += red[t + d];
        __syncthreads();
    }
    if (t == 0) bsum[blockIdx.x] = red[0];
}

__global__ __launch_bounds__(256)
void scan_p2_kernel(const int* __restrict__ bsum, int* __restrict__ boff,
                    int* __restrict__ rowptr, int n, int nb) {
    __shared__ int sm[256];
    int t = threadIdx.x;
    int v = (t < nb) ? bsum[t] : 0;
    sm[t] = v;
    __syncthreads();
    for (int d = 1; d < 256; d <<= 1) {
        int u = (t >= d) ? sm[t - d] : 0;
        __syncthreads();
        sm[t] += u;
        __syncthreads();
    }
    if (t < nb) boff[t] = sm[t] - v;
    if (t == 255) rowptr[n] = sm[255];
}

__global__ __launch_bounds__(256)
void scan_p3_kernel(const int* __restrict__ cnt, const int* __restrict__ boff,
                    int* __restrict__ rowptr, int* __restrict__ cursor, int n) {
    __shared__ int sm[256];
    int base = blockIdx.x * 1024;
    int t = threadIdx.x;
    int c[4];
    int s = 0;
#pragma unroll
    for (int j = 0; j < 4; j++) {
        int i = base + t * 4 + j;
        c[j] = (i < n) ? cnt[i] : 0;
        s += c[j];
    }
    sm[t] = s;
    __syncthreads();
    for (int d = 1; d < 256; d <<= 1) {
        int u = (t >= d) ? sm[t - d] : 0;
        __syncthreads();
        sm[t] += u;
        __syncthreads();
    }
    int run = boff[blockIdx.x] + sm[t] - s;
#pragma unroll
    for (int j = 0; j < 4; j++) {
        int i = base + t * 4 + j;
        if (i < n) { rowptr[i] = run; cursor[i] = run; }
        run += c[j];
    }
}

__global__ void fill_kernel(const int* __restrict__ src, const int* __restrict__ dst,
                            int* __restrict__ cursor, int* __restrict__ esrc, int m) {
    int e = blockIdx.x * blockDim.x + threadIdx.x;
    if (e >= m) return;
    int s = src[e];
    int d = dst[e];
    int pos = atomicAdd(&cursor[d], 1);
    esrc[pos] = s;
}

// ---------------------------------------------------------------------------
// Fused prep: zero cnt; W1/2/3 -> fp16 transposed [n][k]; x -> fp16 into F.
// ---------------------------------------------------------------------------
__device__ __forceinline__ void wcvt(const float* W, unsigned short* Bt,
                                     int idx, int K, int N) {
    int n = idx % N;
    int k = idx / N;
    Bt[n * K + k] = __half_as_ushort(__float2half_rn(W[idx]));
}

__global__ void prep_all_kernel(const float* __restrict__ W1,
                                const float* __restrict__ W2,
                                const float* __restrict__ W3,
                                const float* __restrict__ x, __half* __restrict__ F,
                                unsigned short* __restrict__ B1,
                                unsigned short* __restrict__ B2,
                                unsigned short* __restrict__ B3,
                                int* __restrict__ cnt, int n) {
    int idx = blockIdx.x * 256 + threadIdx.x;
    if (idx < n) cnt[idx] = 0;
    if (idx < 16384) {
        wcvt(W1, B1, idx, 128, 128);
    } else if (idx < 16384 + 8192) {
        wcvt(W2, B2, idx - 16384, 128, 64);
    } else if (idx < 16384 + 8192 + 4096) {
        wcvt(W3, B3, idx - 16384 - 8192, 64, 64);
    } else {
        int j = idx - 28672;
        if (j < n * 32) {
            float4 v = ((const float4*)x)[j];
            uint2 p;
            p.x = h2_as_u32(__floats2half2_rn(v.x, v.y));
            p.y = h2_as_u32(__floats2half2_rn(v.z, v.w));
            ((uint2*)F)[j] = p;
        }
    }
}

// ---------------------------------------------------------------------------
// Tensor-core GEMM: G[M,N] = fp16( dinv[r] * (A[M,K] @ W[K,N]) ), all fp16.
// KC=64 chunked staging (R15-proven). Warp tile 32 rows x N/2 cols (4x2);
// paired-n-frag ldsm_x4 for B.
// ---------------------------------------------------------------------------
template <int K, int N>
__global__ __launch_bounds__(256, 3)
void gemm_mma_kernel(const __half* __restrict__ A,
                     const unsigned short* __restrict__ B,
                     const float* __restrict__ dinv,
                     __half* __restrict__ C, int M) {
    constexpr int KC = 64;
    constexpr int NK = K / KC;
    constexpr int SA = (KC + 8) * 2;     // 144B padded row stride
    constexpr int ABY = 128 * SA;
    extern __shared__ char smem[];
    char* sA = smem;
    char* sB = smem + ABY;

    const int tid = threadIdx.x;
    const int wid = tid >> 5;
    const int lane = tid & 31;
    const int wm = wid & 3;              // 4 M-warps (32 rows)
    const int wn = wid >> 2;             // 2 N-warps (N/2 cols)
    const int rowBase = blockIdx.x * 128;

    constexpr int NF = N / 16;           // n-frags per warp
    float acc[2][NF][4];
#pragma unroll
    for (int mf = 0; mf < 2; mf++)
#pragma unroll
        for (int nf = 0; nf < NF; nf++) {
            acc[mf][nf][0] = 0.f; acc[mf][nf][1] = 0.f;
            acc[mf][nf][2] = 0.f; acc[mf][nf][3] = 0.f;
        }

    const uint32_t aS = smem_u32(sA);
    const uint32_t bS = smem_u32(sB);
    const uint32_t aoff = (uint32_t)(wm * 32 + (lane & 15)) * SA + (uint32_t)(lane >> 4) * 16;
    // paired-n-frag B address: lanes 0-7 nf rows klo, 8-15 nf rows khi,
    // 16-23 nf+1 rows klo, 24-31 nf+1 rows khi
    const uint32_t bbase = bS
                         + (uint32_t)(wn * (N / 2) + (lane & 7) + ((lane >> 4) ? 8 : 0)) * SA
                         + (uint32_t)((lane >> 3) & 1) * 16;

    for (int kc = 0; kc < NK; kc++) {
        if (kc) __syncthreads();

        // stage W chunk: N rows x 64 k (8 x 16B per row)
        for (int i = tid; i < N * 8; i += 256) {
            int r = i >> 3, c = i & 7;
            cp_async16(bS + (uint32_t)(r * SA + c * 16),
                       &B[(size_t)r * K + kc * KC + c * 8]);
        }
        // stage A chunk: 128 rows x 64 k fp16
        for (int i = tid; i < 128 * 8; i += 256) {
            int r = i >> 3, c = i & 7;
            int row = rowBase + r;
            if (row < M)
                cp_async16(aS + (uint32_t)(r * SA + c * 16),
                           &A[(size_t)row * K + kc * KC + c * 8]);
        }
        cp_async_wait_all();
        __syncthreads();

#pragma unroll
        for (int kk = 0; kk < KC / 16; kk++) {
            uint32_t a0[4], a1[4];
            ldsm_x4(a0[0], a0[1], a0[2], a0[3], aS + aoff + kk * 32);
            ldsm_x4(a1[0], a1[1], a1[2], a1[3], aS + aoff + 16 * SA + kk * 32);
#pragma unroll
            for (int np = 0; np < NF / 2; np++) {
                uint32_t b0, b1, b2, b3;
                ldsm_x4(b0, b1, b2, b3, bbase + (uint32_t)(np * 16) * SA + kk * 32);
                mma_fp16(acc[0][2 * np],     a0[0], a0[1], a0[2], a0[3], b0, b1);
                mma_fp16(acc[1][2 * np],     a1[0], a1[1], a1[2], a1[3], b0, b1);
                mma_fp16(acc[0][2 * np + 1], a0[0], a0[1], a0[2], a0[3], b2, b3);
                mma_fp16(acc[1][2 * np + 1], a1[0], a1[1], a1[2], a1[3], b2, b3);
            }
        }
    }

    // epilogue: scale by dinv[row], convert to fp16, store
    int colBase = wn * (N / 2) + (lane & 3) * 2;
#pragma unroll
    for (int mf = 0; mf < 2; mf++) {
        int r0 = rowBase + wm * 32 + mf * 16 + (lane >> 2);
        float s0 = (r0 < M)     ? dinv[r0]     : 0.f;
        float s1 = (r0 + 8 < M) ? dinv[r0 + 8] : 0.f;
#pragma unroll
        for (int nf = 0; nf < NF; nf++) {
            int c0 = colBase + nf * 8;
            if (r0 < M)
                *(__half2*)&C[(size_t)r0 * N + c0] =
                    __floats2half2_rn(acc[mf][nf][0] * s0, acc[mf][nf][1] * s0);
            if (r0 + 8 < M)
                *(__half2*)&C[(size_t)(r0 + 8) * N + c0] =
                    __floats2half2_rn(acc[mf][nf][2] * s1, acc[mf][nf][3] * s1);
        }
    }
}

// ---------------------------------------------------------------------------
// CSR pull aggregation on fp16 G: out_i = b + dinv_i*(G_i + sum G_src).
// OUTHALF=1 -> fp16 feature output; else fp32 (final layer -> d_out).
// ---------------------------------------------------------------------------
template <int F, int RELU, int OUTHALF>
__global__ __launch_bounds__(256)
void aggregate_kernel(const __half* __restrict__ G,
                      const int* __restrict__ rowptr,
                      const int* __restrict__ esrc,
                      const float* __restrict__ dinv,
                      const float* __restrict__ bias,
                      void* __restrict__ Outp, int n) {
    constexpr int L = F / 4;
    constexpr int NB = 256 / L;
    int i = blockIdx.x * NB + (threadIdx.x / L);
    int c = threadIdx.x % L;
    if (i >= n) return;

    const uint2* Gc = (const uint2*)G + c;
    constexpr int RS = F / 4;

    float2 a0, a1;
    {
        uint2 u = __ldg(&Gc[(size_t)i * RS]);
        a0 = __half22float2(*reinterpret_cast<__half2*>(&u.x));
        a1 = __half22float2(*reinterpret_cast<__half2*>(&u.y));
    }

    int k   = rowptr[i];
    int end = rowptr[i + 1];

    for (; k + 3 < end; k += 4) {
        int s0 = __ldg(&esrc[k]);
        int s1 = __ldg(&esrc[k + 1]);
        int s2 = __ldg(&esrc[k + 2]);
        int s3 = __ldg(&esrc[k + 3]);
        uint2 u0 = __ldg(&Gc[(size_t)s0 * RS]);
        uint2 u1 = __ldg(&Gc[(size_t)s1 * RS]);
        uint2 u2 = __ldg(&Gc[(size_t)s2 * RS]);
        uint2 u3 = __ldg(&Gc[(size_t)s3 * RS]);
        float2 f;
        f = __half22float2(*reinterpret_cast<__half2*>(&u0.x)); a0.x += f.x; a0.y += f.y;
        f = __half22float2(*reinterpret_cast<__half2*>(&u0.y)); a1.x += f.x; a1.y += f.y;
        f = __half22float2(*reinterpret_cast<__half2*>(&u1.x)); a0.x += f.x; a0.y += f.y;
        f = __half22float2(*reinterpret_cast<__half2*>(&u1.y)); a1.x += f.x; a1.y += f.y;
        f = __half22float2(*reinterpret_cast<__half2*>(&u2.x)); a0.x += f.x; a0.y += f.y;
        f = __half22float2(*reinterpret_cast<__half2*>(&u2.y)); a1.x += f.x; a1.y += f.y;
        f = __half22float2(*reinterpret_cast<__half2*>(&u3.x)); a0.x += f.x; a0.y += f.y;
        f = __half22float2(*reinterpret_cast<__half2*>(&u3.y)); a1.x += f.x; a1.y += f.y;
    }
    for (; k < end; k++) {
        int s0 = __ldg(&esrc[k]);
        uint2 u0 = __ldg(&Gc[(size_t)s0 * RS]);
        float2 f;
        f = __half22float2(*reinterpret_cast<__half2*>(&u0.x)); a0.x += f.x; a0.y += f.y;
        f = __half22float2(*reinterpret_cast<__half2*>(&u0.y)); a1.x += f.x; a1.y += f.y;
    }

    float di = dinv[i];
    float4 b = ((const float4*)bias)[c];
    float4 o;
    o.x = fmaf(a0.x, di, b.x);
    o.y = fmaf(a0.y, di, b.y);
    o.z = fmaf(a1.x, di, b.z);
    o.w = fmaf(a1.y, di, b.w);
    if (RELU) {
        o.x = fmaxf(o.x, 0.f); o.y = fmaxf(o.y, 0.f);
        o.z = fmaxf(o.z, 0.f); o.w = fmaxf(o.w, 0.f);
    }
    if (OUTHALF) {
        __half* Out = (__half*)Outp;
        uint2 p;
        p.x = h2_as_u32(__floats2half2_rn(o.x, o.y));
        p.y = h2_as_u32(__floats2half2_rn(o.z, o.w));
        *(uint2*)&Out[(size_t)i * F + c * 4] = p;
    } else {
        ((float4*)Outp)[(size_t)i * L + c] = o;
    }
}

// ---------------------------------------------------------------------------
// Launch: prep(1, zeroes cnt), hist(2), dinv(3), scan_p1(4), gemm1(5 = ncu),
//         scan_p2, scan_p3, fill, then agg/gemm chain.
// ---------------------------------------------------------------------------
extern "C" void kernel_launch(void* const* d_in, const int* in_sizes, int n_in,
                              void* d_out, int out_size) {
    const float* x  = (const float*)d_in[0];
    const int*   ei = (const int*)  d_in[1];
    const float* W1 = (const float*)d_in[2];
    const float* b1 = (const float*)d_in[3];
    const float* W2 = (const float*)d_in[4];
    const float* b2 = (const float*)d_in[5];
    const float* W3 = (const float*)d_in[6];
    const float* b3 = (const float*)d_in[7];

    const int n = in_sizes[0] / 128;
    const int m = in_sizes[1] / 2;
    const int* src = ei;
    const int* dst = ei + m;

    float* dinv;
    __half *G, *F;
    int *cnt, *rowptr, *cursor, *bsum, *boff, *esrc;
    unsigned short *B1, *B2, *B3;
    cudaGetSymbolAddress((void**)&G,      g_G);
    cudaGetSymbolAddress((void**)&F,      g_F);
    cudaGetSymbolAddress((void**)&cnt,    g_cnt);
    cudaGetSymbolAddress((void**)&rowptr, g_rowptr);
    cudaGetSymbolAddress((void**)&cursor, g_cursor);
    cudaGetSymbolAddress((void**)&dinv,   g_dinv);
    cudaGetSymbolAddress((void**)&esrc,   g_esrc);
    cudaGetSymbolAddress((void**)&bsum,   g_bsum);
    cudaGetSymbolAddress((void**)&boff,   g_boff);
    cudaGetSymbolAddress((void**)&B1,     g_B1);
    cudaGetSymbolAddress((void**)&B2,     g_B2);
    cudaGetSymbolAddress((void**)&B3,     g_B3);

    const int T = 256;
    const int nb = (n + 1023) / 1024;

    constexpr int SM1 = 18432 + 128 * 144;  // 36864
    constexpr int SM2 = 18432 + 64 * 144;   // 27648
    constexpr int SM3 = 18432 + 64 * 144;   // 27648
    cudaFuncSetAttribute(gemm_mma_kernel<128, 128>, cudaFuncAttributeMaxDynamicSharedMemorySize, SM1);
    cudaFuncSetAttribute(gemm_mma_kernel<128, 64>,  cudaFuncAttributeMaxDynamicSharedMemorySize, SM2);
    cudaFuncSetAttribute(gemm_mma_kernel<64, 64>,   cudaFuncAttributeMaxDynamicSharedMemorySize, SM3);

    const int GB = (n + 127) / 128;

    // 1-4: fused prep (zero cnt + W cvt + x->fp16), degree, dinv, scan_p1
    prep_all_kernel<<<(28672 + n * 32 + 255) / 256, 256>>>(
        W1, W2, W3, x, F, B1, B2, B3, cnt, n);
    hist_kernel<<<(m + T - 1) / T, T>>>(dst, cnt, m);
    dinv_kernel<<<(n + T - 1) / T, T>>>(cnt, dinv, n);
    scan_p1_kernel<<<nb, 256>>>(cnt, bsum, n);
    // 5: GEMM1 (ncu window)
    gemm_mma_kernel<128, 128><<<GB, 256, SM1>>>(F, B1, dinv, G, n);
    // 6-8: rest of CSR
    scan_p2_kernel<<<1, 256>>>(bsum, boff, rowptr, n, nb);
    scan_p3_kernel<<<nb, 256>>>(cnt, boff, rowptr, cursor, n);
    fill_kernel<<<(m + T - 1) / T, T>>>(src, dst, cursor, esrc, m);
    // 9-13: aggregate / gemm chain
    aggregate_kernel<128, 1, 1><<<(n + 7) / 8, 256>>>(G, rowptr, esrc, dinv, b1, F, n);
    gemm_mma_kernel<128, 64><<<GB, 256, SM2>>>(F, B2, dinv, G, n);
    aggregate_kernel<64, 1, 1><<<(n + 15) / 16, 256>>>(G, rowptr, esrc, dinv, b2, F, n);
    gemm_mma_kernel<64, 64><<<GB, 256, SM3>>>(F, B3, dinv, G, n);
    aggregate_kernel<64, 0, 0><<<(n + 15) / 16, 256>>>(G, rowptr, esrc, dinv, b3,
                                                       d_out, n);
}